// round 16
// baseline (speedup 1.0000x reference)
#include <cuda_runtime.h>
#include <cuda_bf16.h>
#include <cuda_fp16.h>
#include <cstdint>

// Problem dims
#define MDIM 8192
#define KDIM 4096
#define NDIM 11008

// Tiling: CTA 256x128x64, 16 warps as 8(M) x 2(N), warp tile 32x64
#define BM 256
#define BN 128
#define BK 64
#define KT (KDIM / BK)        // 64 k-tiles
#define STAGES 4

// Padded smem: rows of 64 fp16 padded to 72 (144B) for conflict-free ldmatrix
#define PITCH_B 144
#define A_TILE_B (BM * PITCH_B)          // 36864
#define W_TILE_B (BN * PITCH_B)          // 18432
#define STAGE_B  (A_TILE_B + W_TILE_B)   // 55296
#define SMEM_TOTAL (STAGES * STAGE_B)    // 221184

// Fused convert kernel work split
#define NX_ITEMS (MDIM * KDIM / 4)                    // float4 items for X
#define NW_ITEMS ((size_t)NDIM * KDIM / 16)           // 16-int groups for W
#define CV_THREADS 256
#define NX_BLOCKS ((NX_ITEMS + CV_THREADS - 1) / CV_THREADS)
#define NW_BLOCKS ((unsigned)((NW_ITEMS + CV_THREADS - 1) / CV_THREADS))

// ---------------------------------------------------------------------------
// Static scratch (no allocs allowed)
// ---------------------------------------------------------------------------
__device__ __half g_X[(size_t)MDIM * KDIM];
__device__ __half g_W[(size_t)NDIM * KDIM];

__device__ __forceinline__ uint32_t smem_u32(const void* p) {
    uint32_t a;
    asm("{ .reg .u64 t; cvta.to.shared.u64 t, %1; cvt.u32.u64 %0, t; }" : "=r"(a) : "l"(p));
    return a;
}

__device__ __forceinline__ void cp16(uint32_t s, const void* g) {
    asm volatile("cp.async.cg.shared.global [%0], [%1], 16;" :: "r"(s), "l"(g));
}

__device__ __forceinline__ void ldsm4(uint32_t* r, uint32_t a) {
    asm volatile("ldmatrix.sync.aligned.m8n8.x4.shared.b16 {%0,%1,%2,%3}, [%4];"
                 : "=r"(r[0]), "=r"(r[1]), "=r"(r[2]), "=r"(r[3]) : "r"(a));
}

__device__ __forceinline__ void mma16816(float* d, const uint32_t* a, uint32_t b0, uint32_t b1) {
    asm volatile(
        "mma.sync.aligned.m16n8k16.row.col.f32.f16.f16.f32 "
        "{%0,%1,%2,%3}, {%4,%5,%6,%7}, {%8,%9}, {%0,%1,%2,%3};"
        : "+f"(d[0]), "+f"(d[1]), "+f"(d[2]), "+f"(d[3])
        : "r"(a[0]), "r"(a[1]), "r"(a[2]), "r"(a[3]), "r"(b0), "r"(b1));
}

// ---------------------------------------------------------------------------
// Fused pre-pass: one launch converts X (fp32 -> fp16) and W (int32 -> fp16)
// ---------------------------------------------------------------------------
__global__ void __launch_bounds__(CV_THREADS) convert_fused_kernel(
    const float4* __restrict__ x, const int4* __restrict__ w)
{
    const unsigned b = blockIdx.x;
    if (b < NX_BLOCKS) {
        const int i = b * CV_THREADS + threadIdx.x;
        if (i >= NX_ITEMS) return;
        float4 v = x[i];
        __half2 a2, b2;
        a2.x = __float2half_rn(v.x); a2.y = __float2half_rn(v.y);
        b2.x = __float2half_rn(v.z); b2.y = __float2half_rn(v.w);
        __half2* xp = reinterpret_cast<__half2*>(g_X);
        xp[2*i] = a2; xp[2*i+1] = b2;
    } else {
        const size_t i = (size_t)(b - NX_BLOCKS) * CV_THREADS + threadIdx.x;
        if (i >= NW_ITEMS) return;
        __half2 h[8];
        #pragma unroll
        for (int j = 0; j < 4; j++) {
            int4 v = w[i * 4 + j];
            h[2*j+0].x = __float2half_rn((float)v.x);
            h[2*j+0].y = __float2half_rn((float)v.y);
            h[2*j+1].x = __float2half_rn((float)v.z);
            h[2*j+1].y = __float2half_rn((float)v.w);
        }
        uint4* wp = reinterpret_cast<uint4*>(g_W);
        const uint32_t* hr = reinterpret_cast<const uint32_t*>(h);
        wp[2*i]   = make_uint4(hr[0], hr[1], hr[2], hr[3]);
        wp[2*i+1] = make_uint4(hr[4], hr[5], hr[6], hr[7]);
    }
}

// ---------------------------------------------------------------------------
// Main GEMM: mma.sync fp16, cp.async 4-stage pipeline, 16 warps (4/SMSP),
// warp tile 32x64. Per-warp kstep ROTATION de-phase-locks co-resident warps:
// at any instant, one warp per SMSP does LDSM while the others feed HMMA.
// ---------------------------------------------------------------------------
__global__ void __launch_bounds__(512, 1)
qlinear_gemm(const float* __restrict__ wscale,
             const float* __restrict__ wbias,
             float* __restrict__ out)
{
    extern __shared__ char smem[];
    const uint32_t sb = smem_u32(smem);
    const int tid = threadIdx.x;
    const int wid = tid >> 5;
    const int lane = tid & 31;
    const int m0 = blockIdx.y * BM;
    const int n0 = blockIdx.x * BN;
    const int wm = wid >> 1;   // 0..7 -> 32 rows each
    const int wn = wid & 1;    // 0..1 -> 64 cols each
    // Warps sharing an SMSP have equal wid%4; (wid>>2) enumerates them 0..3.
    const int ksrot = (wid >> 2) & 3;

    const __half* gX = g_X + (size_t)m0 * KDIM;
    const __half* gW = g_W + (size_t)n0 * KDIM;

    float acc[2][8][4];
    #pragma unroll
    for (int a = 0; a < 2; a++)
        #pragma unroll
        for (int b = 0; b < 8; b++)
            #pragma unroll
            for (int c = 0; c < 4; c++) acc[a][b][c] = 0.f;

    // loads: A 2048 + W 1024 16B-chunks per stage / 512 threads = 6 each
    const int lrow0 = tid >> 3;       // 0..63
    const int lcol  = tid & 7;        // 16B chunk within 128B row

    auto load_stage = [&](int s, int kt) {
        const uint32_t base = sb + s * STAGE_B;
        const int k0 = kt * BK;
        #pragma unroll
        for (int i = 0; i < 4; i++) {
            const int r = lrow0 + i * 64;
            cp16(base + r * PITCH_B + lcol * 16, gX + (size_t)r * KDIM + k0 + lcol * 8);
        }
        #pragma unroll
        for (int i = 0; i < 2; i++) {
            const int r = lrow0 + i * 64;
            cp16(base + A_TILE_B + r * PITCH_B + lcol * 16, gW + (size_t)r * KDIM + k0 + lcol * 8);
        }
    };

    auto compute_stage = [&](int s) {
        const uint32_t abase = sb + s * STAGE_B;
        const uint32_t bbase = abase + A_TILE_B;
        const int lr = lane & 15;
        const int lk = (lane >> 4) * 16;
        #pragma unroll
        for (int kk = 0; kk < 4; kk++) {
            const int ks = (kk + ksrot) & 3;     // per-warp rotated kstep order
            uint32_t af[2][4], bf[4][4];
            #pragma unroll
            for (int mt = 0; mt < 2; mt++) {
                uint32_t ro = (uint32_t)(wm * 32 + mt * 16 + lr) * PITCH_B + ks * 32 + lk;
                ldsm4(af[mt], abase + ro);
            }
            #pragma unroll
            for (int nt = 0; nt < 4; nt++) {
                uint32_t ro = (uint32_t)(wn * 64 + nt * 16 + lr) * PITCH_B + ks * 32 + lk;
                ldsm4(bf[nt], bbase + ro);
            }
            #pragma unroll
            for (int mt = 0; mt < 2; mt++) {
                #pragma unroll
                for (int nt = 0; nt < 4; nt++) {
                    mma16816(acc[mt][nt*2+0], af[mt], bf[nt][0], bf[nt][2]);
                    mma16816(acc[mt][nt*2+1], af[mt], bf[nt][1], bf[nt][3]);
                }
            }
        }
    };

    load_stage(0, 0);
    asm volatile("cp.async.commit_group;" ::: "memory");
    load_stage(1, 1);
    asm volatile("cp.async.commit_group;" ::: "memory");
    load_stage(2, 2);
    asm volatile("cp.async.commit_group;" ::: "memory");

    for (int kt = 0; kt < KT; kt++) {
        asm volatile("cp.async.wait_group 2;" ::: "memory");
        __syncthreads();
        if (kt + 3 < KT) {
            load_stage((kt + 3) & 3, kt + 3);
        }
        asm volatile("cp.async.commit_group;" ::: "memory");
        compute_stage(kt & 3);
    }

    // Epilogue: scale + bias (fp32 inputs), fp32 store
    #pragma unroll
    for (int mt = 0; mt < 2; mt++) {
        const int r0 = m0 + wm * 32 + mt * 16 + (lane >> 2);
        #pragma unroll
        for (int nt = 0; nt < 4; nt++) {
            #pragma unroll
            for (int h = 0; h < 2; h++) {
                const int n = n0 + wn * 64 + nt * 16 + h * 8 + (lane & 3) * 2;
                float2 sf = *reinterpret_cast<const float2*>(wscale + n);
                float2 bf = *reinterpret_cast<const float2*>(wbias + n);
                const float* d = acc[mt][nt*2+h];
                float2 v0, v1;
                v0.x = d[0] * sf.x + bf.x;
                v0.y = d[1] * sf.y + bf.y;
                v1.x = d[2] * sf.x + bf.x;
                v1.y = d[3] * sf.y + bf.y;
                *reinterpret_cast<float2*>(out + (size_t)r0 * NDIM + n) = v0;
                *reinterpret_cast<float2*>(out + (size_t)(r0 + 8) * NDIM + n) = v1;
            }
        }
    }
}

// ---------------------------------------------------------------------------
// Host
// ---------------------------------------------------------------------------
extern "C" void kernel_launch(void* const* d_in, const int* in_sizes, int n_in,
                              void* d_out, int out_size) {
    const float* x  = (const float*)d_in[0];
    const int*   wq = (const int*)d_in[1];
    const float* sc = (const float*)d_in[2];
    const float* bi = (const float*)d_in[3];
    float* out = (float*)d_out;

    convert_fused_kernel<<<NX_BLOCKS + NW_BLOCKS, CV_THREADS>>>(
        (const float4*)x, (const int4*)wq);

    cudaFuncSetAttribute(qlinear_gemm, cudaFuncAttributeMaxDynamicSharedMemorySize, SMEM_TOTAL);
    dim3 grid(NDIM / BN, MDIM / BM);   // (86, 32), n-fastest for W L2 reuse
    qlinear_gemm<<<grid, 512, SMEM_TOTAL>>>(sc, bi, out);
}

// round 17
// speedup vs baseline: 1.0881x; 1.0881x over previous
#include <cuda_runtime.h>
#include <cuda_bf16.h>
#include <cuda_fp16.h>
#include <cstdint>

// Problem dims
#define MDIM 8192
#define KDIM 4096
#define NDIM 11008

// Tiling: CTA 128x128x64, 8 warps as 4(M) x 2(N), warp tile 32x64
// Small smem footprint -> 2 CTAs/SM -> independent barrier epochs overlap.
#define BM 128
#define BN 128
#define BK 64
#define KT (KDIM / BK)        // 64 k-tiles
#define STAGES 3

// Padded smem: rows of 64 fp16 padded to 72 (144B) for conflict-free ldmatrix
#define PITCH_B 144
#define A_TILE_B (BM * PITCH_B)          // 18432
#define W_TILE_B (BN * PITCH_B)          // 18432
#define STAGE_B  (A_TILE_B + W_TILE_B)   // 36864
#define SMEM_TOTAL (STAGES * STAGE_B)    // 110592 -> 2 CTAs per SM

// Fused convert kernel work split
#define NX_ITEMS (MDIM * KDIM / 4)                    // float4 items for X
#define NW_ITEMS ((size_t)NDIM * KDIM / 16)           // 16-int groups for W
#define CV_THREADS 256
#define NX_BLOCKS ((NX_ITEMS + CV_THREADS - 1) / CV_THREADS)
#define NW_BLOCKS ((unsigned)((NW_ITEMS + CV_THREADS - 1) / CV_THREADS))

// ---------------------------------------------------------------------------
// Static scratch (no allocs allowed)
// ---------------------------------------------------------------------------
__device__ __half g_X[(size_t)MDIM * KDIM];
__device__ __half g_W[(size_t)NDIM * KDIM];

__device__ __forceinline__ uint32_t smem_u32(const void* p) {
    uint32_t a;
    asm("{ .reg .u64 t; cvta.to.shared.u64 t, %1; cvt.u32.u64 %0, t; }" : "=r"(a) : "l"(p));
    return a;
}

__device__ __forceinline__ void cp16(uint32_t s, const void* g) {
    asm volatile("cp.async.cg.shared.global [%0], [%1], 16;" :: "r"(s), "l"(g));
}

__device__ __forceinline__ void ldsm4(uint32_t* r, uint32_t a) {
    asm volatile("ldmatrix.sync.aligned.m8n8.x4.shared.b16 {%0,%1,%2,%3}, [%4];"
                 : "=r"(r[0]), "=r"(r[1]), "=r"(r[2]), "=r"(r[3]) : "r"(a));
}

__device__ __forceinline__ void mma16816(float* d, const uint32_t* a, uint32_t b0, uint32_t b1) {
    asm volatile(
        "mma.sync.aligned.m16n8k16.row.col.f32.f16.f16.f32 "
        "{%0,%1,%2,%3}, {%4,%5,%6,%7}, {%8,%9}, {%0,%1,%2,%3};"
        : "+f"(d[0]), "+f"(d[1]), "+f"(d[2]), "+f"(d[3])
        : "r"(a[0]), "r"(a[1]), "r"(a[2]), "r"(a[3]), "r"(b0), "r"(b1));
}

// ---------------------------------------------------------------------------
// Fused pre-pass: one launch converts X (fp32 -> fp16) and W (int32 -> fp16)
// ---------------------------------------------------------------------------
__global__ void __launch_bounds__(CV_THREADS) convert_fused_kernel(
    const float4* __restrict__ x, const int4* __restrict__ w)
{
    const unsigned b = blockIdx.x;
    if (b < NX_BLOCKS) {
        const int i = b * CV_THREADS + threadIdx.x;
        if (i >= NX_ITEMS) return;
        float4 v = x[i];
        __half2 a2, b2;
        a2.x = __float2half_rn(v.x); a2.y = __float2half_rn(v.y);
        b2.x = __float2half_rn(v.z); b2.y = __float2half_rn(v.w);
        __half2* xp = reinterpret_cast<__half2*>(g_X);
        xp[2*i] = a2; xp[2*i+1] = b2;
    } else {
        const size_t i = (size_t)(b - NX_BLOCKS) * CV_THREADS + threadIdx.x;
        if (i >= NW_ITEMS) return;
        __half2 h[8];
        #pragma unroll
        for (int j = 0; j < 4; j++) {
            int4 v = w[i * 4 + j];
            h[2*j+0].x = __float2half_rn((float)v.x);
            h[2*j+0].y = __float2half_rn((float)v.y);
            h[2*j+1].x = __float2half_rn((float)v.z);
            h[2*j+1].y = __float2half_rn((float)v.w);
        }
        uint4* wp = reinterpret_cast<uint4*>(g_W);
        const uint32_t* hr = reinterpret_cast<const uint32_t*>(h);
        wp[2*i]   = make_uint4(hr[0], hr[1], hr[2], hr[3]);
        wp[2*i+1] = make_uint4(hr[4], hr[5], hr[6], hr[7]);
    }
}

// ---------------------------------------------------------------------------
// Main GEMM: mma.sync fp16, cp.async 3-stage pipeline, 2 CTAs/SM
// ---------------------------------------------------------------------------
__global__ void __launch_bounds__(256, 2)
qlinear_gemm(const float* __restrict__ wscale,
             const float* __restrict__ wbias,
             float* __restrict__ out)
{
    extern __shared__ char smem[];
    const uint32_t sb = smem_u32(smem);
    const int tid = threadIdx.x;
    const int wid = tid >> 5;
    const int lane = tid & 31;
    const int m0 = blockIdx.y * BM;
    const int n0 = blockIdx.x * BN;
    const int wm = wid >> 1;   // 0..3 -> 32 rows each
    const int wn = wid & 1;    // 0..1 -> 64 cols each

    const __half* gX = g_X + (size_t)m0 * KDIM;
    const __half* gW = g_W + (size_t)n0 * KDIM;

    float acc[2][8][4];
    #pragma unroll
    for (int a = 0; a < 2; a++)
        #pragma unroll
        for (int b = 0; b < 8; b++)
            #pragma unroll
            for (int c = 0; c < 4; c++) acc[a][b][c] = 0.f;

    // loads: A 1024 + W 1024 16B-chunks per stage / 256 threads = 8 each
    const int lrow0 = tid >> 3;       // 0..31
    const int lcol  = tid & 7;        // 16B chunk within 128B row

    auto load_stage = [&](int s, int kt) {
        const uint32_t base = sb + s * STAGE_B;
        const int k0 = kt * BK;
        #pragma unroll
        for (int i = 0; i < 4; i++) {
            const int r = lrow0 + i * 32;
            const uint32_t soff = r * PITCH_B + lcol * 16;
            const size_t goff = (size_t)r * KDIM + k0 + lcol * 8;
            cp16(base + soff,            gX + goff);
            cp16(base + A_TILE_B + soff, gW + goff);
        }
    };

    auto compute_stage = [&](int s) {
        const uint32_t abase = sb + s * STAGE_B;
        const uint32_t bbase = abase + A_TILE_B;
        const int lr = lane & 15;
        const int lk = (lane >> 4) * 16;
        #pragma unroll
        for (int ks = 0; ks < 4; ks++) {
            uint32_t af[2][4], bf[4][4];
            #pragma unroll
            for (int mt = 0; mt < 2; mt++) {
                uint32_t ro = (uint32_t)(wm * 32 + mt * 16 + lr) * PITCH_B + ks * 32 + lk;
                ldsm4(af[mt], abase + ro);
            }
            #pragma unroll
            for (int nt = 0; nt < 4; nt++) {
                uint32_t ro = (uint32_t)(wn * 64 + nt * 16 + lr) * PITCH_B + ks * 32 + lk;
                ldsm4(bf[nt], bbase + ro);
            }
            #pragma unroll
            for (int mt = 0; mt < 2; mt++) {
                #pragma unroll
                for (int nt = 0; nt < 4; nt++) {
                    mma16816(acc[mt][nt*2+0], af[mt], bf[nt][0], bf[nt][2]);
                    mma16816(acc[mt][nt*2+1], af[mt], bf[nt][1], bf[nt][3]);
                }
            }
        }
    };

    // Prologue: stages 0,1
    load_stage(0, 0);
    asm volatile("cp.async.commit_group;" ::: "memory");
    load_stage(1, 1);
    asm volatile("cp.async.commit_group;" ::: "memory");

    for (int kt = 0; kt < KT; kt++) {
        asm volatile("cp.async.wait_group 1;" ::: "memory");
        __syncthreads();
        if (kt + 2 < KT) {
            int s = kt + 2;
            s = s - (s / 3) * 3;               // (kt+2) % 3
            load_stage(s, kt + 2);
        }
        asm volatile("cp.async.commit_group;" ::: "memory");
        compute_stage(kt - (kt / 3) * 3);       // kt % 3
    }

    // Epilogue: scale + bias (fp32 inputs), fp32 store
    #pragma unroll
    for (int mt = 0; mt < 2; mt++) {
        const int r0 = m0 + wm * 32 + mt * 16 + (lane >> 2);
        #pragma unroll
        for (int nt = 0; nt < 4; nt++) {
            #pragma unroll
            for (int h = 0; h < 2; h++) {
                const int n = n0 + wn * 64 + nt * 16 + h * 8 + (lane & 3) * 2;
                float2 sf = *reinterpret_cast<const float2*>(wscale + n);
                float2 bf = *reinterpret_cast<const float2*>(wbias + n);
                const float* d = acc[mt][nt*2+h];
                float2 v0, v1;
                v0.x = d[0] * sf.x + bf.x;
                v0.y = d[1] * sf.y + bf.y;
                v1.x = d[2] * sf.x + bf.x;
                v1.y = d[3] * sf.y + bf.y;
                *reinterpret_cast<float2*>(out + (size_t)r0 * NDIM + n) = v0;
                *reinterpret_cast<float2*>(out + (size_t)(r0 + 8) * NDIM + n) = v1;
            }
        }
    }
}

// ---------------------------------------------------------------------------
// Host
// ---------------------------------------------------------------------------
extern "C" void kernel_launch(void* const* d_in, const int* in_sizes, int n_in,
                              void* d_out, int out_size) {
    const float* x  = (const float*)d_in[0];
    const int*   wq = (const int*)d_in[1];
    const float* sc = (const float*)d_in[2];
    const float* bi = (const float*)d_in[3];
    float* out = (float*)d_out;

    convert_fused_kernel<<<NX_BLOCKS + NW_BLOCKS, CV_THREADS>>>(
        (const float4*)x, (const int4*)wq);

    cudaFuncSetAttribute(qlinear_gemm, cudaFuncAttributeMaxDynamicSharedMemorySize, SMEM_TOTAL);
    dim3 grid(NDIM / BN, MDIM / BM);   // (86, 64), n-fastest for W L2 reuse
    qlinear_gemm<<<grid, 256, SMEM_TOTAL>>>(sc, bi, out);
}